// round 12
// baseline (speedup 1.0000x reference)
#include <cuda_runtime.h>
#include <cuda_fp16.h>
#include <cstdint>
#include <math.h>

#define BSZ   8
#define TLEN  4096
#define INF   256
#define HDIM  512
#define OUTF  256
#define MROWS (BSZ*TLEN)     /* 32768 */
#define CHUNK 64
#define NC    (TLEN/CHUNK)   /* 64 */

/* ---------------- scratch (device globals; no runtime allocation) -------- */
__device__ __align__(16) float g_A [(size_t)MROWS*HDIM];
__device__ __align__(16) float g_Bv[(size_t)MROWS*HDIM];
__device__ __align__(16) unsigned short g_in_h[(size_t)MROWS*INF];     /* fp16 */
__device__ __align__(16) unsigned short g_Wg_hi[3*HDIM*INF];  /* [1536][256] */
__device__ __align__(16) unsigned short g_Wg_lo[3*HDIM*INF];
__device__ __align__(16) unsigned short g_wo_h[OUTF*HDIM];    /* [256][512]  */
__device__ __align__(16) unsigned short g_h_hi[(size_t)MROWS*HDIM];
__device__ __align__(16) float g_sA[BSZ*NC*HDIM];
__device__ __align__(16) float g_sB[BSZ*NC*HDIM];
__device__ __align__(16) float g_sR[BSZ*NC*HDIM];
__device__ __align__(16) float g_bound[BSZ*NC*HDIM];

__device__ __forceinline__ float sigf(float x) {
    return 1.0f / (1.0f + __expf(-x));
}

__device__ __forceinline__ uint32_t smem_u32(const void* p) {
    uint32_t a;
    asm("{ .reg .u64 t; cvta.to.shared.u64 t, %1; cvt.u32.u64 %0, t; }"
        : "=r"(a) : "l"(p));
    return a;
}

#define CP_ASYNC16(dst, src) \
    asm volatile("cp.async.cg.shared.global [%0], [%1], 16;" :: "r"(dst), "l"(src))
#define CP_COMMIT()  asm volatile("cp.async.commit_group;" ::: "memory")
#define CP_WAIT(N)   asm volatile("cp.async.wait_group %0;" :: "n"(N) : "memory")

__device__ __forceinline__ void ldsm4(uint32_t r[4], uint32_t addr) {
    asm volatile("ldmatrix.sync.aligned.m8n8.x4.shared.b16 {%0,%1,%2,%3}, [%4];"
        : "=r"(r[0]), "=r"(r[1]), "=r"(r[2]), "=r"(r[3]) : "r"(addr));
}

__device__ __forceinline__ void mma_f16(float c[4], const uint32_t a[4],
                                        uint32_t b0, uint32_t b1) {
    asm volatile(
        "mma.sync.aligned.m16n8k16.row.col.f32.f16.f16.f32 "
        "{%0,%1,%2,%3}, {%4,%5,%6,%7}, {%8,%9}, {%0,%1,%2,%3};"
        : "+f"(c[0]), "+f"(c[1]), "+f"(c[2]), "+f"(c[3])
        : "r"(a[0]), "r"(a[1]), "r"(a[2]), "r"(a[3]), "r"(b0), "r"(b1));
}

/* ====================== conversion / split kernels ======================= */
__global__ void conv_input_kernel(const float* __restrict__ x)
{
    int i = blockIdx.x * blockDim.x + threadIdx.x;       /* per float4 */
    float4 v = ((const float4*)x)[i];
    ushort4 hv;
    hv.x = __half_as_ushort(__float2half_rn(v.x));
    hv.y = __half_as_ushort(__float2half_rn(v.y));
    hv.z = __half_as_ushort(__float2half_rn(v.z));
    hv.w = __half_as_ushort(__float2half_rn(v.w));
    ((ushort4*)g_in_h)[i] = hv;
}

__global__ void conv_whg_kernel(const float* __restrict__ W)
{
    int i = blockIdx.x * blockDim.x + threadIdx.x;  /* i = n*256 + k */
    int n = i >> 8, k = i & 255;
    float v = W[(size_t)k * (3 * HDIM) + n];
    __half h = __float2half_rn(v);
    g_Wg_hi[i] = __half_as_ushort(h);
    g_Wg_lo[i] = __half_as_ushort(__float2half_rn(v - __half2float(h)));
}

__global__ void conv_wout_kernel(const float* __restrict__ W)
{
    int i = blockIdx.x * blockDim.x + threadIdx.x;  /* i = n*512 + k */
    int n = i >> 9, k = i & 511;
    g_wo_h[i] = __half_as_ushort(__float2half_rn(W[(size_t)k * OUTF + n]));
}

/* =========================================================================
 * Gates GEMM (fp16 2-pass: in_fp16 x (W_hi + W_lo)) + fused sigmoid
 * epilogue + fused per-chunk scan summary (fold reads L2-hot globals).
 * CTA: 256 thr, 128 m x 192 n. Warps 2m x 4n -> warp tile 64m x 48n.
 * K=256 in 8 chunks of 32, cp.async 4-stage pipeline.
 * ========================================================================= */
#define G1_A    0
#define G1_BHI  10240
#define G1_BLO  25600
#define G1_STG  40960
#define G1_PA   100352
#define G1_PB   101376
#define G1_PR   102400
#define G1_SMEM (4 * G1_STG)     /* 163840; epilogue overlaps dead stages */
#define SPITCH  196

__global__ __launch_bounds__(256, 1)
void gates_mma_kernel(const int* __restrict__ is_init)
{
    extern __shared__ char smem[];
    uint32_t sb = smem_u32(smem);
    const int tid = threadIdx.x, lane = tid & 31, wid = tid >> 5;
    const int m0 = blockIdx.x * 128, h0 = blockIdx.y * 64;
    const int wm = wid >> 2, wn = wid & 3;     /* 2m x 4n */

    float acc[4][6][4];
    #pragma unroll
    for (int a = 0; a < 4; ++a)
        #pragma unroll
        for (int b = 0; b < 6; ++b)
            acc[a][b][0] = acc[a][b][1] = acc[a][b][2] = acc[a][b][3] = 0.f;

    const char* aG = (const char*)g_in_h;
    const char* bH = (const char*)g_Wg_hi;
    const char* bL = (const char*)g_Wg_lo;

    /* ---- chunk loader: 2048 x 16B segments, 8 per thread (256 thr) ---- */
    #define G1_LOAD(c) do {                                                   \
        uint32_t stg = sb + ((c) & 3) * G1_STG;                               \
        int k0 = (c) * 32;                                                    \
        _Pragma("unroll")                                                     \
        for (int it = 0; it < 8; ++it) {                                      \
            int idx = tid + it * 256;                                         \
            if (idx < 512) {                                                  \
                int r = idx >> 2, sg = idx & 3;                               \
                const char* src = aG                                          \
                    + ((size_t)(m0 + r) * INF + k0) * 2 + sg * 16;            \
                CP_ASYNC16(stg + G1_A + r * 80 + sg * 16, src);               \
            } else {                                                          \
                int j = idx - 512;                                            \
                int sp = (j >= 768) ? 1 : 0, rem = j - sp * 768;              \
                int r = rem >> 2, sg = rem & 3;                               \
                const char* src = (sp ? bL : bH)                              \
                    + ((size_t)((r >> 6) * HDIM + h0 + (r & 63)) * INF + k0) * 2 \
                    + sg * 16;                                                \
                CP_ASYNC16(stg + (sp ? G1_BLO : G1_BHI) + r * 80 + sg * 16, src); \
            }                                                                 \
        }                                                                     \
        CP_COMMIT();                                                          \
    } while (0)

    G1_LOAD(0); G1_LOAD(1); G1_LOAD(2);
    #pragma unroll 1
    for (int c = 0; c < 8; ++c) {
        if (c <= 5)      { CP_WAIT(2); }
        else if (c == 6) { CP_WAIT(1); }
        else             { CP_WAIT(0); }
        __syncthreads();
        if (c + 3 < 8) G1_LOAD(c + 3);
        uint32_t stg = sb + (c & 3) * G1_STG;

        #pragma unroll
        for (int ks = 0; ks < 2; ++ks) {
            const int kb = ks * 32;                 /* 16 elems = 32 bytes */
            uint32_t ah[4][4];
            #pragma unroll
            for (int mi = 0; mi < 4; ++mi) {
                uint32_t ad = stg + G1_A
                    + (wm * 64 + mi * 16 + (lane & 15)) * 80
                    + (lane >> 4) * 16 + kb;
                ldsm4(ah[mi], ad);
            }
            #pragma unroll
            for (int j = 0; j < 3; ++j) {
                uint32_t bh[4], bl[4];
                int r = wn * 48 + j * 16 + ((lane >> 4) << 3) + (lane & 7);
                uint32_t bd = stg + G1_BHI + r * 80
                    + ((lane >> 3) & 1) * 16 + kb;
                ldsm4(bh, bd);
                ldsm4(bl, bd + (G1_BLO - G1_BHI));
                #pragma unroll
                for (int mi = 0; mi < 4; ++mi)
                    #pragma unroll
                    for (int s = 0; s < 2; ++s) {
                        int nb = j * 2 + s;
                        mma_f16(acc[mi][nb], ah[mi], bh[s*2], bh[s*2+1]);
                        mma_f16(acc[mi][nb], ah[mi], bl[s*2], bl[s*2+1]);
                    }
            }
        }
    }
    __syncthreads();

    /* ---- epilogue: stage accums, fuse sigmoid ---- */
    float* spad = (float*)smem;
    #pragma unroll
    for (int mi = 0; mi < 4; ++mi)
        #pragma unroll
        for (int nb = 0; nb < 6; ++nb) {
            int row = wm * 64 + mi * 16 + (lane >> 2);
            int col = wn * 48 + nb * 8 + (lane & 3) * 2;
            spad[row * SPITCH + col]           = acc[mi][nb][0];
            spad[row * SPITCH + col + 1]       = acc[mi][nb][1];
            spad[(row + 8) * SPITCH + col]     = acc[mi][nb][2];
            spad[(row + 8) * SPITCH + col + 1] = acc[mi][nb][3];
        }
    __syncthreads();

    const int h4 = (tid & 15) * 4, mr = tid >> 4;    /* mr: 0..15 */
    #pragma unroll
    for (int i = 0; i < 8; ++i) {
        int m = mr + i * 16;
        float4 gf = *(float4*)&spad[m * SPITCH + h4];
        float4 gi = *(float4*)&spad[m * SPITCH + 64 + h4];
        float4 gh = *(float4*)&spad[m * SPITCH + 128 + h4];
        float4 A4, B4;
        A4.x = sigf(gf.x); A4.y = sigf(gf.y);
        A4.z = sigf(gf.z); A4.w = sigf(gf.w);
        B4.x = sigf(gi.x) * gh.x; B4.y = sigf(gi.y) * gh.y;
        B4.z = sigf(gi.z) * gh.z; B4.w = sigf(gi.w) * gh.w;
        size_t base = (size_t)(m0 + m) * HDIM + h0 + h4;
        *(float4*)&g_A [base] = A4;
        *(float4*)&g_Bv[base] = B4;
    }
    __syncthreads();

    /* ---- fused chunk summary: 2 chunks x 64 h; 2-way fold from L2 ---- */
    {
        const int q = tid >> 7, l = tid & 127;        /* q: half of chunk  */
        const int cl = l >> 6, hl = l & 63;
        const int bb = m0 >> 12;
        const int tloc = (m0 & 4095) + cl * 64 + q * 32;
        const int* ip = is_init + bb * TLEN + tloc;
        size_t gidx = ((size_t)(m0 + cl * 64 + q * 32)) * HDIM + h0 + hl;
        float A = 1.f, Bv = 0.f, r = 0.f;
        #pragma unroll 8
        for (int s = 0; s < 32; ++s, gidx += HDIM) {
            float a  = g_A[gidx];
            float bv = g_Bv[gidx];
            if (ip[s]) { A = a; Bv = bv; r = 1.f; }
            else       { Bv = fmaf(a, Bv, bv); A *= a; }
        }
        float* PA = (float*)(smem + G1_PA);
        float* PB = (float*)(smem + G1_PB);
        float* PR = (float*)(smem + G1_PR);
        PA[q * 128 + l] = A; PB[q * 128 + l] = Bv; PR[q * 128 + l] = r;
    }
    __syncthreads();
    if (tid < 128) {
        const int l = tid, cl = l >> 6, hl = l & 63;
        float* PA = (float*)(smem + G1_PA);
        float* PB = (float*)(smem + G1_PB);
        float* PR = (float*)(smem + G1_PR);
        float A = PA[l], Bv = PB[l], r = PR[l];
        float A2 = PA[128 + l], B2 = PB[128 + l], r2 = PR[128 + l];
        if (r2 > 0.f) { A = A2; Bv = B2; r = 1.f; }
        else          { Bv = fmaf(A2, Bv, B2); A *= A2; }
        const int bb = m0 >> 12, c0 = (m0 & 4095) >> 6;
        int sidx = (bb * NC + c0 + cl) * HDIM + h0 + hl;
        g_sA[sidx] = A; g_sB[sidx] = Bv; g_sR[sidx] = r;
    }
}

/* =========================================================================
 * Output GEMM: out = h_fp16 @ W_out_fp16 (single pass).  256 thr,
 * 128m x 128n, K=512 in 16 chunks. Warps 2m x 4n, warp 64m x 32n.
 * 4-stage pipeline.
 * ========================================================================= */
#define G2_A    0
#define G2_B    10240
#define G2_STG  20480
#define G2_SMEM (4 * G2_STG)     /* 81920 */

__global__ __launch_bounds__(256, 1) void out_mma_kernel(float* __restrict__ out)
{
    extern __shared__ char smem[];
    uint32_t sb = smem_u32(smem);
    const int tid = threadIdx.x, lane = tid & 31, wid = tid >> 5;
    const int m0 = blockIdx.x * 128, n0 = blockIdx.y * 128;
    const int wm = wid >> 2, wn = wid & 3;     /* 2m x 4n */

    float acc[4][4][4];
    #pragma unroll
    for (int a = 0; a < 4; ++a)
        #pragma unroll
        for (int b = 0; b < 4; ++b)
            acc[a][b][0] = acc[a][b][1] = acc[a][b][2] = acc[a][b][3] = 0.f;

    const char* aG = (const char*)g_h_hi;
    const char* bG = (const char*)g_wo_h;

    /* 1024 segments, 4 per thread */
    #define G2_LOAD(c) do {                                                   \
        uint32_t stg = sb + ((c) & 3) * G2_STG;                               \
        int k0 = (c) * 32;                                                    \
        _Pragma("unroll")                                                     \
        for (int it = 0; it < 4; ++it) {                                      \
            int idx = tid + it * 256;                                         \
            if (idx < 512) {                                                  \
                int r = idx >> 2, sg = idx & 3;                               \
                const char* src = aG                                          \
                    + ((size_t)(m0 + r) * HDIM + k0) * 2 + sg * 16;           \
                CP_ASYNC16(stg + G2_A + r * 80 + sg * 16, src);               \
            } else {                                                          \
                int j = idx - 512;                                            \
                int r = j >> 2, sg = j & 3;                                   \
                const char* src = bG                                          \
                    + ((size_t)(n0 + r) * HDIM + k0) * 2 + sg * 16;           \
                CP_ASYNC16(stg + G2_B + r * 80 + sg * 16, src);               \
            }                                                                 \
        }                                                                     \
        CP_COMMIT();                                                          \
    } while (0)

    G2_LOAD(0); G2_LOAD(1); G2_LOAD(2);
    #pragma unroll 1
    for (int c = 0; c < 16; ++c) {
        if (c <= 13)      { CP_WAIT(2); }
        else if (c == 14) { CP_WAIT(1); }
        else              { CP_WAIT(0); }
        __syncthreads();
        if (c + 3 < 16) G2_LOAD(c + 3);
        uint32_t stg = sb + (c & 3) * G2_STG;

        #pragma unroll
        for (int ks = 0; ks < 2; ++ks) {
            const int kb = ks * 32;
            uint32_t ah[4][4];
            #pragma unroll
            for (int mi = 0; mi < 4; ++mi) {
                uint32_t ad = stg + G2_A
                    + (wm * 64 + mi * 16 + (lane & 15)) * 80
                    + (lane >> 4) * 16 + kb;
                ldsm4(ah[mi], ad);
            }
            #pragma unroll
            for (int j = 0; j < 2; ++j) {
                uint32_t bh[4];
                int r = wn * 32 + j * 16 + ((lane >> 4) << 3) + (lane & 7);
                uint32_t bd = stg + G2_B + r * 80
                    + ((lane >> 3) & 1) * 16 + kb;
                ldsm4(bh, bd);
                #pragma unroll
                for (int mi = 0; mi < 4; ++mi)
                    #pragma unroll
                    for (int s = 0; s < 2; ++s) {
                        int nb = j * 2 + s;
                        mma_f16(acc[mi][nb], ah[mi], bh[s*2], bh[s*2+1]);
                    }
            }
        }
    }

    /* direct epilogue */
    #pragma unroll
    for (int mi = 0; mi < 4; ++mi)
        #pragma unroll
        for (int nb = 0; nb < 4; ++nb) {
            int row = m0 + wm * 64 + mi * 16 + (lane >> 2);
            int col = n0 + wn * 32 + nb * 8 + (lane & 3) * 2;
            *(float2*)&out[(size_t)row * OUTF + col] =
                make_float2(acc[mi][nb][0], acc[mi][nb][1]);
            *(float2*)&out[(size_t)(row + 8) * OUTF + col] =
                make_float2(acc[mi][nb][2], acc[mi][nb][3]);
        }
}

/* ======================== scan kernels ================================== */
__global__ void chunk_scan_kernel(const float* __restrict__ h0p)
{
    int lane = blockIdx.x * blockDim.x + threadIdx.x;   /* < BSZ*H */
    int h = lane & (HDIM - 1);
    int b = lane >> 9;
    float h0v = h0p[b * HDIM + h];
    float hp = h0v;
    #pragma unroll 4
    for (int c = 0; c < NC; ++c) {
        int s = (b * NC + c) * HDIM + h;
        g_bound[s] = hp;
        float prev = (g_sR[s] > 0.f) ? h0v : hp;
        hp = fmaf(g_sA[s], prev, g_sB[s]);
    }
}

__global__ void apply_scan_kernel(const int* __restrict__ is_init,
                                  const float* __restrict__ h0p,
                                  float* __restrict__ hn_out)
{
    int lane = blockIdx.x * blockDim.x + threadIdx.x;
    int h  = lane & (HDIM - 1);
    int bc = lane >> 9;
    int c  = bc & (NC - 1);
    int b  = bc >> 6;
    int t0 = c * CHUNK;

    float h0v = h0p[b * HDIM + h];
    float hv  = g_bound[lane];
    size_t idx = ((size_t)(b * TLEN + t0)) * HDIM + h;
    const int* ip = is_init + b * TLEN + t0;

    #pragma unroll 4
    for (int t = 0; t < CHUNK; ++t, idx += HDIM) {
        float a  = g_A[idx];
        float bv = g_Bv[idx];
        float prev = ip[t] ? h0v : hv;
        hv = fmaf(a, prev, bv);
        g_h_hi[idx] = __half_as_ushort(__float2half_rn(hv));
    }
    if (c == NC - 1) hn_out[b * HDIM + h] = hv;
}

/* ========================================================================= */
extern "C" void kernel_launch(void* const* d_in, const int* in_sizes, int n_in,
                              void* d_out, int out_size)
{
    const float* inp  = (const float*)d_in[0];   /* (8,4096,256)  */
    const int*   isin = (const int*)  d_in[1];   /* (8,4096,1)    */
    const float* h0   = (const float*)d_in[2];   /* (8,1,512)     */
    const float* Whg  = (const float*)d_in[3];   /* (256,1536)    */
    const float* Wout = (const float*)d_in[4];   /* (512,256)     */
    float* out = (float*)d_out;                  /* out then h_n  */

    cudaFuncSetAttribute(gates_mma_kernel,
                         cudaFuncAttributeMaxDynamicSharedMemorySize, G1_SMEM);
    cudaFuncSetAttribute(out_mma_kernel,
                         cudaFuncAttributeMaxDynamicSharedMemorySize, G2_SMEM);

    conv_input_kernel<<<(MROWS * INF / 4) / 256, 256>>>(inp);
    conv_whg_kernel<<<(3 * HDIM * INF) / 256, 256>>>(Whg);
    conv_wout_kernel<<<(OUTF * HDIM) / 256, 256>>>(Wout);

    gates_mma_kernel<<<dim3(MROWS / 128, HDIM / 64), 256, G1_SMEM>>>(isin);

    chunk_scan_kernel<<<(BSZ * HDIM) / 256, 256>>>(h0);
    apply_scan_kernel<<<(BSZ * NC * HDIM) / 256, 256>>>(isin, h0,
                                                        out + (size_t)MROWS * OUTF);

    out_mma_kernel<<<dim3(MROWS / 128, OUTF / 128), 256, G2_SMEM>>>(out);
}

// round 13
// speedup vs baseline: 1.0873x; 1.0873x over previous
#include <cuda_runtime.h>
#include <cuda_fp16.h>
#include <cstdint>
#include <math.h>

#define BSZ   8
#define TLEN  4096
#define INF   256
#define HDIM  512
#define OUTF  256
#define MROWS (BSZ*TLEN)     /* 32768 */
#define CHUNK 64
#define NC    (TLEN/CHUNK)   /* 64 */

/* ---------------- scratch (device globals; no runtime allocation) -------- */
__device__ __align__(16) float g_A [(size_t)MROWS*HDIM];
__device__ __align__(16) float g_Bv[(size_t)MROWS*HDIM];
__device__ __align__(16) unsigned short g_in_h[(size_t)MROWS*INF];     /* fp16 */
__device__ __align__(16) unsigned short g_Wg_hi[3*HDIM*INF];  /* [1536][256] */
__device__ __align__(16) unsigned short g_Wg_lo[3*HDIM*INF];
__device__ __align__(16) unsigned short g_wo_h[OUTF*HDIM];    /* [256][512]  */
__device__ __align__(16) unsigned short g_h_hi[(size_t)MROWS*HDIM];
__device__ __align__(16) float g_sA[BSZ*NC*HDIM];
__device__ __align__(16) float g_sB[BSZ*NC*HDIM];
__device__ __align__(16) float g_sR[BSZ*NC*HDIM];
__device__ __align__(16) float g_bound[BSZ*NC*HDIM];

__device__ __forceinline__ float sigf(float x) {
    return 1.0f / (1.0f + __expf(-x));
}

__device__ __forceinline__ uint32_t smem_u32(const void* p) {
    uint32_t a;
    asm("{ .reg .u64 t; cvta.to.shared.u64 t, %1; cvt.u32.u64 %0, t; }"
        : "=r"(a) : "l"(p));
    return a;
}

#define CP_ASYNC16(dst, src) \
    asm volatile("cp.async.cg.shared.global [%0], [%1], 16;" :: "r"(dst), "l"(src))
#define CP_COMMIT()  asm volatile("cp.async.commit_group;" ::: "memory")
#define CP_WAIT(N)   asm volatile("cp.async.wait_group %0;" :: "n"(N) : "memory")

__device__ __forceinline__ void ldsm4(uint32_t r[4], uint32_t addr) {
    asm volatile("ldmatrix.sync.aligned.m8n8.x4.shared.b16 {%0,%1,%2,%3}, [%4];"
        : "=r"(r[0]), "=r"(r[1]), "=r"(r[2]), "=r"(r[3]) : "r"(addr));
}

__device__ __forceinline__ void mma_f16(float c[4], const uint32_t a[4],
                                        uint32_t b0, uint32_t b1) {
    asm volatile(
        "mma.sync.aligned.m16n8k16.row.col.f32.f16.f16.f32 "
        "{%0,%1,%2,%3}, {%4,%5,%6,%7}, {%8,%9}, {%0,%1,%2,%3};"
        : "+f"(c[0]), "+f"(c[1]), "+f"(c[2]), "+f"(c[3])
        : "r"(a[0]), "r"(a[1]), "r"(a[2]), "r"(a[3]), "r"(b0), "r"(b1));
}

/* ====================== conversion / split kernels ======================= */
__global__ void conv_input_kernel(const float* __restrict__ x)
{
    int i = blockIdx.x * blockDim.x + threadIdx.x;       /* per float4 */
    float4 v = ((const float4*)x)[i];
    ushort4 hv;
    hv.x = __half_as_ushort(__float2half_rn(v.x));
    hv.y = __half_as_ushort(__float2half_rn(v.y));
    hv.z = __half_as_ushort(__float2half_rn(v.z));
    hv.w = __half_as_ushort(__float2half_rn(v.w));
    ((ushort4*)g_in_h)[i] = hv;
}

__global__ void conv_whg_kernel(const float* __restrict__ W)
{
    int i = blockIdx.x * blockDim.x + threadIdx.x;  /* i = n*256 + k */
    int n = i >> 8, k = i & 255;
    float v = W[(size_t)k * (3 * HDIM) + n];
    __half h = __float2half_rn(v);
    g_Wg_hi[i] = __half_as_ushort(h);
    g_Wg_lo[i] = __half_as_ushort(__float2half_rn(v - __half2float(h)));
}

__global__ void conv_wout_kernel(const float* __restrict__ W)
{
    int i = blockIdx.x * blockDim.x + threadIdx.x;  /* i = n*512 + k */
    int n = i >> 9, k = i & 511;
    g_wo_h[i] = __half_as_ushort(__float2half_rn(W[(size_t)k * OUTF + n]));
}

/* =========================================================================
 * Gates GEMM (fp16 2-pass: in_fp16 x (W_hi + W_lo)) + fused sigmoid
 * epilogue + fused per-chunk scan summary.
 * CTA: 512 thr, 128 m x (3 gates x 64 h). Warps 4m x 4n, warp 32m x 48n.
 * K=256 in 8 chunks of 32, cp.async 4-stage pipeline.
 * ks order is SKEWED by warp group so half the warps per SMSP are in the
 * ldsm phase while the other half are in the mma phase.
 * ========================================================================= */
#define G1_A    0
#define G1_BHI  10240
#define G1_BLO  25600
#define G1_STG  40960
#define G1_AS   100352
#define G1_BS   135168
#define G1_PA   169984
#define G1_PB   172032
#define G1_PR   174080
#define G1_SMEM 176128
#define SPITCH  196
#define APITCH  68

__global__ __launch_bounds__(512, 1)
void gates_mma_kernel(const int* __restrict__ is_init)
{
    extern __shared__ char smem[];
    uint32_t sb = smem_u32(smem);
    const int tid = threadIdx.x, lane = tid & 31, wid = tid >> 5;
    const int m0 = blockIdx.x * 128, h0 = blockIdx.y * 64;
    const int wm = wid >> 2, wn = wid & 3;
    const int phase = (wid >> 2) & 1;          /* per-SMSP phase skew */

    float acc[2][6][4];
    #pragma unroll
    for (int a = 0; a < 2; ++a)
        #pragma unroll
        for (int b = 0; b < 6; ++b)
            acc[a][b][0] = acc[a][b][1] = acc[a][b][2] = acc[a][b][3] = 0.f;

    const char* aG = (const char*)g_in_h;
    const char* bH = (const char*)g_Wg_hi;
    const char* bL = (const char*)g_Wg_lo;

    /* ---- chunk loader: 2048 x 16B segments, 4 per thread ---- */
    #define G1_LOAD(c) do {                                                   \
        uint32_t stg = sb + ((c) & 3) * G1_STG;                               \
        int k0 = (c) * 32;                                                    \
        _Pragma("unroll")                                                     \
        for (int it = 0; it < 4; ++it) {                                      \
            int idx = tid + it * 512;                                         \
            if (idx < 512) {                                                  \
                int r = idx >> 2, sg = idx & 3;                               \
                const char* src = aG                                          \
                    + ((size_t)(m0 + r) * INF + k0) * 2 + sg * 16;            \
                CP_ASYNC16(stg + G1_A + r * 80 + sg * 16, src);               \
            } else {                                                          \
                int j = idx - 512;                                            \
                int sp = (j >= 768) ? 1 : 0, rem = j - sp * 768;              \
                int r = rem >> 2, sg = rem & 3;                               \
                const char* src = (sp ? bL : bH)                              \
                    + ((size_t)((r >> 6) * HDIM + h0 + (r & 63)) * INF + k0) * 2 \
                    + sg * 16;                                                \
                CP_ASYNC16(stg + (sp ? G1_BLO : G1_BHI) + r * 80 + sg * 16, src); \
            }                                                                 \
        }                                                                     \
        CP_COMMIT();                                                          \
    } while (0)

    G1_LOAD(0); G1_LOAD(1); G1_LOAD(2);
    #pragma unroll 1
    for (int c = 0; c < 8; ++c) {
        if (c <= 5)      { CP_WAIT(2); }
        else if (c == 6) { CP_WAIT(1); }
        else             { CP_WAIT(0); }
        __syncthreads();
        if (c + 3 < 8) G1_LOAD(c + 3);
        uint32_t stg = sb + (c & 3) * G1_STG;

        #pragma unroll
        for (int kss = 0; kss < 2; ++kss) {
            const int ks = kss ^ phase;             /* skewed half-step */
            const int kb = ks * 32;                 /* 16 elems = 32 bytes */
            uint32_t ah[2][4];
            #pragma unroll
            for (int mi = 0; mi < 2; ++mi) {
                uint32_t ad = stg + G1_A
                    + (wm * 32 + mi * 16 + (lane & 15)) * 80
                    + (lane >> 4) * 16 + kb;
                ldsm4(ah[mi], ad);
            }
            #pragma unroll
            for (int j = 0; j < 3; ++j) {
                uint32_t bh[4], bl[4];
                int r = wn * 48 + j * 16 + ((lane >> 4) << 3) + (lane & 7);
                uint32_t bd = stg + G1_BHI + r * 80
                    + ((lane >> 3) & 1) * 16 + kb;
                ldsm4(bh, bd);
                ldsm4(bl, bd + (G1_BLO - G1_BHI));
                #pragma unroll
                for (int mi = 0; mi < 2; ++mi)
                    #pragma unroll
                    for (int s = 0; s < 2; ++s) {
                        int nb = j * 2 + s;
                        mma_f16(acc[mi][nb], ah[mi], bh[s*2], bh[s*2+1]);
                        mma_f16(acc[mi][nb], ah[mi], bl[s*2], bl[s*2+1]);
                    }
            }
        }
    }
    __syncthreads();

    /* ---- epilogue: stage accums, fuse sigmoid ---- */
    float* spad = (float*)smem;
    #pragma unroll
    for (int mi = 0; mi < 2; ++mi)
        #pragma unroll
        for (int nb = 0; nb < 6; ++nb) {
            int row = wm * 32 + mi * 16 + (lane >> 2);
            int col = wn * 48 + nb * 8 + (lane & 3) * 2;
            spad[row * SPITCH + col]           = acc[mi][nb][0];
            spad[row * SPITCH + col + 1]       = acc[mi][nb][1];
            spad[(row + 8) * SPITCH + col]     = acc[mi][nb][2];
            spad[(row + 8) * SPITCH + col + 1] = acc[mi][nb][3];
        }
    __syncthreads();

    float* As = (float*)(smem + G1_AS);
    float* Bs = (float*)(smem + G1_BS);
    const int h4 = (tid & 15) * 4, mr = tid >> 4;    /* mr: 0..31 */
    #pragma unroll
    for (int i = 0; i < 4; ++i) {
        int m = mr + i * 32;
        float4 gf = *(float4*)&spad[m * SPITCH + h4];
        float4 gi = *(float4*)&spad[m * SPITCH + 64 + h4];
        float4 gh = *(float4*)&spad[m * SPITCH + 128 + h4];
        float4 A4, B4;
        A4.x = sigf(gf.x); A4.y = sigf(gf.y);
        A4.z = sigf(gf.z); A4.w = sigf(gf.w);
        B4.x = sigf(gi.x) * gh.x; B4.y = sigf(gi.y) * gh.y;
        B4.z = sigf(gi.z) * gh.z; B4.w = sigf(gi.w) * gh.w;
        size_t base = (size_t)(m0 + m) * HDIM + h0 + h4;
        *(float4*)&g_A [base] = A4;
        *(float4*)&g_Bv[base] = B4;
        *(float4*)&As[m * APITCH + h4] = A4;
        *(float4*)&Bs[m * APITCH + h4] = B4;
    }
    __syncthreads();

    /* ---- fused chunk summary: 2 chunks x 64 h, 4-way fold + combine ---- */
    {
        const int q = tid >> 7, l = tid & 127;
        const int cl = l >> 6, hl = l & 63;
        const int bb = m0 >> 12;
        const int lr0 = cl * 64 + q * 16;
        const int* ip = is_init + bb * TLEN + (m0 & 4095) + lr0;
        float A = 1.f, Bv = 0.f, r = 0.f;
        #pragma unroll
        for (int s = 0; s < 16; ++s) {
            float a  = As[(lr0 + s) * APITCH + hl];
            float bv = Bs[(lr0 + s) * APITCH + hl];
            if (ip[s]) { A = a; Bv = bv; r = 1.f; }
            else       { Bv = fmaf(a, Bv, bv); A *= a; }
        }
        float* PA = (float*)(smem + G1_PA);
        float* PB = (float*)(smem + G1_PB);
        float* PR = (float*)(smem + G1_PR);
        PA[q * 128 + l] = A; PB[q * 128 + l] = Bv; PR[q * 128 + l] = r;
    }
    __syncthreads();
    if (tid < 128) {
        const int l = tid, cl = l >> 6, hl = l & 63;
        float* PA = (float*)(smem + G1_PA);
        float* PB = (float*)(smem + G1_PB);
        float* PR = (float*)(smem + G1_PR);
        float A = PA[l], Bv = PB[l], r = PR[l];
        #pragma unroll
        for (int q = 1; q < 4; ++q) {
            float A2 = PA[q * 128 + l], B2 = PB[q * 128 + l], r2 = PR[q * 128 + l];
            if (r2 > 0.f) { A = A2; Bv = B2; r = 1.f; }
            else          { Bv = fmaf(A2, Bv, B2); A *= A2; }
        }
        const int bb = m0 >> 12, c0 = (m0 & 4095) >> 6;
        int sidx = (bb * NC + c0 + cl) * HDIM + h0 + hl;
        g_sA[sidx] = A; g_sB[sidx] = Bv; g_sR[sidx] = r;
    }
}

/* =========================================================================
 * Output GEMM: out = h_fp16 @ W_out_fp16 (single pass).  512 thr,
 * 128m x 128n, K=512 in 16 chunks. Warps 4m x 4n, warp 32m x 32n.
 * 4-stage pipeline, skewed ks order.
 * ========================================================================= */
#define G2_A    0
#define G2_B    10240
#define G2_STG  20480
#define G2_SMEM (4 * G2_STG)     /* 81920 */

__global__ __launch_bounds__(512, 1) void out_mma_kernel(float* __restrict__ out)
{
    extern __shared__ char smem[];
    uint32_t sb = smem_u32(smem);
    const int tid = threadIdx.x, lane = tid & 31, wid = tid >> 5;
    const int m0 = blockIdx.x * 128, n0 = blockIdx.y * 128;
    const int wm = wid >> 2, wn = wid & 3;
    const int phase = (wid >> 2) & 1;

    float acc[2][4][4];
    #pragma unroll
    for (int a = 0; a < 2; ++a)
        #pragma unroll
        for (int b = 0; b < 4; ++b)
            acc[a][b][0] = acc[a][b][1] = acc[a][b][2] = acc[a][b][3] = 0.f;

    const char* aG = (const char*)g_h_hi;
    const char* bG = (const char*)g_wo_h;

    /* 1024 segments, 2 per thread */
    #define G2_LOAD(c) do {                                                   \
        uint32_t stg = sb + ((c) & 3) * G2_STG;                               \
        int k0 = (c) * 32;                                                    \
        _Pragma("unroll")                                                     \
        for (int it = 0; it < 2; ++it) {                                      \
            int idx = tid + it * 512;                                         \
            if (idx < 512) {                                                  \
                int r = idx >> 2, sg = idx & 3;                               \
                const char* src = aG                                          \
                    + ((size_t)(m0 + r) * HDIM + k0) * 2 + sg * 16;           \
                CP_ASYNC16(stg + G2_A + r * 80 + sg * 16, src);               \
            } else {                                                          \
                int j = idx - 512;                                            \
                int r = j >> 2, sg = j & 3;                                   \
                const char* src = bG                                          \
                    + ((size_t)(n0 + r) * HDIM + k0) * 2 + sg * 16;           \
                CP_ASYNC16(stg + G2_B + r * 80 + sg * 16, src);               \
            }                                                                 \
        }                                                                     \
        CP_COMMIT();                                                          \
    } while (0)

    G2_LOAD(0); G2_LOAD(1); G2_LOAD(2);
    #pragma unroll 1
    for (int c = 0; c < 16; ++c) {
        if (c <= 13)      { CP_WAIT(2); }
        else if (c == 14) { CP_WAIT(1); }
        else              { CP_WAIT(0); }
        __syncthreads();
        if (c + 3 < 16) G2_LOAD(c + 3);
        uint32_t stg = sb + (c & 3) * G2_STG;

        #pragma unroll
        for (int kss = 0; kss < 2; ++kss) {
            const int ks = kss ^ phase;
            const int kb = ks * 32;
            uint32_t ah[2][4];
            #pragma unroll
            for (int mi = 0; mi < 2; ++mi) {
                uint32_t ad = stg + G2_A
                    + (wm * 32 + mi * 16 + (lane & 15)) * 80
                    + (lane >> 4) * 16 + kb;
                ldsm4(ah[mi], ad);
            }
            #pragma unroll
            for (int j = 0; j < 2; ++j) {
                uint32_t bh[4];
                int r = wn * 32 + j * 16 + ((lane >> 4) << 3) + (lane & 7);
                uint32_t bd = stg + G2_B + r * 80
                    + ((lane >> 3) & 1) * 16 + kb;
                ldsm4(bh, bd);
                #pragma unroll
                for (int mi = 0; mi < 2; ++mi)
                    #pragma unroll
                    for (int s = 0; s < 2; ++s) {
                        int nb = j * 2 + s;
                        mma_f16(acc[mi][nb], ah[mi], bh[s*2], bh[s*2+1]);
                    }
            }
        }
    }

    /* direct epilogue */
    #pragma unroll
    for (int mi = 0; mi < 2; ++mi)
        #pragma unroll
        for (int nb = 0; nb < 4; ++nb) {
            int row = m0 + wm * 32 + mi * 16 + (lane >> 2);
            int col = n0 + wn * 32 + nb * 8 + (lane & 3) * 2;
            *(float2*)&out[(size_t)row * OUTF + col] =
                make_float2(acc[mi][nb][0], acc[mi][nb][1]);
            *(float2*)&out[(size_t)(row + 8) * OUTF + col] =
                make_float2(acc[mi][nb][2], acc[mi][nb][3]);
        }
}

/* ======================== scan kernels ================================== */
__global__ void chunk_scan_kernel(const float* __restrict__ h0p)
{
    int lane = blockIdx.x * blockDim.x + threadIdx.x;   /* < BSZ*H */
    int h = lane & (HDIM - 1);
    int b = lane >> 9;
    float h0v = h0p[b * HDIM + h];
    float hp = h0v;
    #pragma unroll 4
    for (int c = 0; c < NC; ++c) {
        int s = (b * NC + c) * HDIM + h;
        g_bound[s] = hp;
        float prev = (g_sR[s] > 0.f) ? h0v : hp;
        hp = fmaf(g_sA[s], prev, g_sB[s]);
    }
}

__global__ void apply_scan_kernel(const int* __restrict__ is_init,
                                  const float* __restrict__ h0p,
                                  float* __restrict__ hn_out)
{
    int lane = blockIdx.x * blockDim.x + threadIdx.x;
    int h  = lane & (HDIM - 1);
    int bc = lane >> 9;
    int c  = bc & (NC - 1);
    int b  = bc >> 6;
    int t0 = c * CHUNK;

    float h0v = h0p[b * HDIM + h];
    float hv  = g_bound[lane];
    size_t idx = ((size_t)(b * TLEN + t0)) * HDIM + h;
    const int* ip = is_init + b * TLEN + t0;

    #pragma unroll 4
    for (int t = 0; t < CHUNK; ++t, idx += HDIM) {
        float a  = g_A[idx];
        float bv = g_Bv[idx];
        float prev = ip[t] ? h0v : hv;
        hv = fmaf(a, prev, bv);
        g_h_hi[idx] = __half_as_ushort(__float2half_rn(hv));
    }
    if (c == NC - 1) hn_out[b * HDIM + h] = hv;
}

/* ========================================================================= */
extern "C" void kernel_launch(void* const* d_in, const int* in_sizes, int n_in,
                              void* d_out, int out_size)
{
    const float* inp  = (const float*)d_in[0];   /* (8,4096,256)  */
    const int*   isin = (const int*)  d_in[1];   /* (8,4096,1)    */
    const float* h0   = (const float*)d_in[2];   /* (8,1,512)     */
    const float* Whg  = (const float*)d_in[3];   /* (256,1536)    */
    const float* Wout = (const float*)d_in[4];   /* (512,256)     */
    float* out = (float*)d_out;                  /* out then h_n  */

    cudaFuncSetAttribute(gates_mma_kernel,
                         cudaFuncAttributeMaxDynamicSharedMemorySize, G1_SMEM);
    cudaFuncSetAttribute(out_mma_kernel,
                         cudaFuncAttributeMaxDynamicSharedMemorySize, G2_SMEM);

    conv_input_kernel<<<(MROWS * INF / 4) / 256, 256>>>(inp);
    conv_whg_kernel<<<(3 * HDIM * INF) / 256, 256>>>(Whg);
    conv_wout_kernel<<<(OUTF * HDIM) / 256, 256>>>(Wout);

    gates_mma_kernel<<<dim3(MROWS / 128, HDIM / 64), 512, G1_SMEM>>>(isin);

    chunk_scan_kernel<<<(BSZ * HDIM) / 256, 256>>>(h0);
    apply_scan_kernel<<<(BSZ * NC * HDIM) / 256, 256>>>(isin, h0,
                                                        out + (size_t)MROWS * OUTF);

    out_mma_kernel<<<dim3(MROWS / 128, OUTF / 128), 512, G2_SMEM>>>(out);
}

// round 15
// speedup vs baseline: 1.1977x; 1.1016x over previous
#include <cuda_runtime.h>
#include <cuda_fp16.h>
#include <cstdint>
#include <math.h>

#define BSZ   8
#define TLEN  4096
#define INF   256
#define HDIM  512
#define OUTF  256
#define MROWS (BSZ*TLEN)     /* 32768 */
#define CHUNK 64
#define NC    (TLEN/CHUNK)   /* 64 */

/* ---------------- scratch (device globals; no runtime allocation) -------- */
__device__ __align__(16) float g_A [(size_t)MROWS*HDIM];
__device__ __align__(16) float g_Bv[(size_t)MROWS*HDIM];
__device__ __align__(16) unsigned short g_in_h[(size_t)MROWS*INF];     /* fp16 */
__device__ __align__(16) unsigned short g_Wg_hi[3*HDIM*INF];  /* [1536][256] */
__device__ __align__(16) unsigned short g_Wg_lo[3*HDIM*INF];
__device__ __align__(16) unsigned short g_wo_h[OUTF*HDIM];    /* [256][512]  */
__device__ __align__(16) unsigned short g_h_hi[(size_t)MROWS*HDIM];
__device__ __align__(16) float g_sA[BSZ*NC*HDIM];
__device__ __align__(16) float g_sB[BSZ*NC*HDIM];
__device__ __align__(16) float g_sR[BSZ*NC*HDIM];
__device__ __align__(16) float g_bound[BSZ*NC*HDIM];

__device__ __forceinline__ float sigf(float x) {
    return 1.0f / (1.0f + __expf(-x));
}

__device__ __forceinline__ uint32_t smem_u32(const void* p) {
    uint32_t a;
    asm("{ .reg .u64 t; cvta.to.shared.u64 t, %1; cvt.u32.u64 %0, t; }"
        : "=r"(a) : "l"(p));
    return a;
}

#define CP_ASYNC16(dst, src) \
    asm volatile("cp.async.cg.shared.global [%0], [%1], 16;" :: "r"(dst), "l"(src))
#define CP_COMMIT()  asm volatile("cp.async.commit_group;" ::: "memory")
#define CP_WAIT(N)   asm volatile("cp.async.wait_group %0;" :: "n"(N) : "memory")

__device__ __forceinline__ void ldsm4(uint32_t r[4], uint32_t addr) {
    asm volatile("ldmatrix.sync.aligned.m8n8.x4.shared.b16 {%0,%1,%2,%3}, [%4];"
        : "=r"(r[0]), "=r"(r[1]), "=r"(r[2]), "=r"(r[3]) : "r"(addr));
}

__device__ __forceinline__ void mma_f16(float c[4], const uint32_t a[4],
                                        uint32_t b0, uint32_t b1) {
    asm volatile(
        "mma.sync.aligned.m16n8k16.row.col.f32.f16.f16.f32 "
        "{%0,%1,%2,%3}, {%4,%5,%6,%7}, {%8,%9}, {%0,%1,%2,%3};"
        : "+f"(c[0]), "+f"(c[1]), "+f"(c[2]), "+f"(c[3])
        : "r"(a[0]), "r"(a[1]), "r"(a[2]), "r"(a[3]), "r"(b0), "r"(b1));
}

/* ====================== conversion / split kernels ======================= */
__global__ void conv_input_kernel(const float* __restrict__ x)
{
    int i = blockIdx.x * blockDim.x + threadIdx.x;       /* per float4 */
    float4 v = ((const float4*)x)[i];
    ushort4 hv;
    hv.x = __half_as_ushort(__float2half_rn(v.x));
    hv.y = __half_as_ushort(__float2half_rn(v.y));
    hv.z = __half_as_ushort(__float2half_rn(v.z));
    hv.w = __half_as_ushort(__float2half_rn(v.w));
    ((ushort4*)g_in_h)[i] = hv;
}

__global__ void conv_whg_kernel(const float* __restrict__ W)
{
    int i = blockIdx.x * blockDim.x + threadIdx.x;  /* i = n*256 + k */
    int n = i >> 8, k = i & 255;
    float v = W[(size_t)k * (3 * HDIM) + n];
    __half h = __float2half_rn(v);
    g_Wg_hi[i] = __half_as_ushort(h);
    g_Wg_lo[i] = __half_as_ushort(__float2half_rn(v - __half2float(h)));
}

__global__ void conv_wout_kernel(const float* __restrict__ W)
{
    int i = blockIdx.x * blockDim.x + threadIdx.x;  /* i = n*512 + k */
    int n = i >> 9, k = i & 511;
    g_wo_h[i] = __half_as_ushort(__float2half_rn(W[(size_t)k * OUTF + n]));
}

/* =========================================================================
 * Gates GEMM (fp16 2-pass) + fused sigmoid + fused chunk summary.
 * CTA: 256 thr, 128 m x 96 n (3 gates x 32 h). Warps 4m x 2n -> 32m x 48n.
 * K=256 in 8 chunks of 32, 4-stage cp.async pipeline. 2 CTAs/SM.
 * Stage: A 128x80 = 10240, B (96 hi + 96 lo) x 80 = 15360 -> 25600.
 * Epilogue spad (128x100 f32 = 51200) + partials overlap dead stages.
 * ========================================================================= */
#define G1_B    10240
#define G1_STG  25600
#define G1_PA   51200
#define G1_PB   52224
#define G1_PR   53248
#define G1_SMEM (4 * G1_STG)     /* 102400 */
#define SPITCH  100

__global__ __launch_bounds__(256, 2)
void gates_mma_kernel(const int* __restrict__ is_init)
{
    extern __shared__ char smem[];
    uint32_t sb = smem_u32(smem);
    const int tid = threadIdx.x, lane = tid & 31, wid = tid >> 5;
    const int m0 = blockIdx.x * 128, h0 = blockIdx.y * 32;
    const int wm = wid >> 1, wn = wid & 1;     /* 4m x 2n */
    const int phase = (wid >> 2) & 1;          /* per-SMSP phase skew */

    float acc[2][6][4];
    #pragma unroll
    for (int a = 0; a < 2; ++a)
        #pragma unroll
        for (int b = 0; b < 6; ++b)
            acc[a][b][0] = acc[a][b][1] = acc[a][b][2] = acc[a][b][3] = 0.f;

    const char* aG = (const char*)g_in_h;
    const char* bH = (const char*)g_Wg_hi;
    const char* bL = (const char*)g_Wg_lo;

    /* ---- chunk loader: 1280 x 16B segments, 5 per thread ---- */
    #define G1_LOAD(c) do {                                                   \
        uint32_t stg = sb + ((c) & 3) * G1_STG;                               \
        int k0 = (c) * 32;                                                    \
        _Pragma("unroll")                                                     \
        for (int it = 0; it < 5; ++it) {                                      \
            int idx = tid + it * 256;                                         \
            if (idx < 512) {                                                  \
                int r = idx >> 2, sg = idx & 3;                               \
                const char* src = aG                                          \
                    + ((size_t)(m0 + r) * INF + k0) * 2 + sg * 16;            \
                CP_ASYNC16(stg + r * 80 + sg * 16, src);                      \
            } else {                                                          \
                int j = idx - 512;                                            \
                int sp = (j >= 384) ? 1 : 0, rem = j - sp * 384;              \
                int r = rem >> 2, sg = rem & 3;                               \
                int n = (r >> 5) * HDIM + h0 + (r & 31);                      \
                const char* src = (sp ? bL : bH)                              \
                    + ((size_t)n * INF + k0) * 2 + sg * 16;                   \
                CP_ASYNC16(stg + G1_B + (sp * 96 + r) * 80 + sg * 16, src);   \
            }                                                                 \
        }                                                                     \
        CP_COMMIT();                                                          \
    } while (0)

    G1_LOAD(0); G1_LOAD(1); G1_LOAD(2);
    #pragma unroll 1
    for (int c = 0; c < 8; ++c) {
        if (c <= 5)      { CP_WAIT(2); }
        else if (c == 6) { CP_WAIT(1); }
        else             { CP_WAIT(0); }
        __syncthreads();
        if (c + 3 < 8) G1_LOAD(c + 3);
        uint32_t stg = sb + (c & 3) * G1_STG;

        #pragma unroll
        for (int kss = 0; kss < 2; ++kss) {
            const int ks = kss ^ phase;             /* skewed half-step */
            const int kb = ks * 32;                 /* 16 elems = 32 bytes */
            uint32_t ah[2][4];
            #pragma unroll
            for (int mi = 0; mi < 2; ++mi) {
                uint32_t ad = stg
                    + (wm * 32 + mi * 16 + (lane & 15)) * 80
                    + (lane >> 4) * 16 + kb;
                ldsm4(ah[mi], ad);
            }
            #pragma unroll
            for (int j = 0; j < 3; ++j) {
                uint32_t bh[4], bl[4];
                int r = wn * 48 + j * 16 + ((lane >> 4) << 3) + (lane & 7);
                uint32_t bd = stg + G1_B + r * 80
                    + ((lane >> 3) & 1) * 16 + kb;
                ldsm4(bh, bd);
                ldsm4(bl, bd + 96 * 80);
                #pragma unroll
                for (int mi = 0; mi < 2; ++mi)
                    #pragma unroll
                    for (int s = 0; s < 2; ++s) {
                        int nb = j * 2 + s;
                        mma_f16(acc[mi][nb], ah[mi], bh[s*2], bh[s*2+1]);
                        mma_f16(acc[mi][nb], ah[mi], bl[s*2], bl[s*2+1]);
                    }
            }
        }
    }
    __syncthreads();

    /* ---- epilogue: stage accums, fuse sigmoid ---- */
    float* spad = (float*)smem;
    #pragma unroll
    for (int mi = 0; mi < 2; ++mi)
        #pragma unroll
        for (int nb = 0; nb < 6; ++nb) {
            int row = wm * 32 + mi * 16 + (lane >> 2);
            int col = wn * 48 + nb * 8 + (lane & 3) * 2;
            spad[row * SPITCH + col]           = acc[mi][nb][0];
            spad[row * SPITCH + col + 1]       = acc[mi][nb][1];
            spad[(row + 8) * SPITCH + col]     = acc[mi][nb][2];
            spad[(row + 8) * SPITCH + col + 1] = acc[mi][nb][3];
        }
    __syncthreads();

    const int h4 = (tid & 7) * 4, mr = tid >> 3;     /* mr: 0..31 */
    #pragma unroll
    for (int i = 0; i < 4; ++i) {
        int m = mr + i * 32;
        float4 gf = *(float4*)&spad[m * SPITCH + h4];
        float4 gi = *(float4*)&spad[m * SPITCH + 32 + h4];
        float4 gh = *(float4*)&spad[m * SPITCH + 64 + h4];
        float4 A4, B4;
        A4.x = sigf(gf.x); A4.y = sigf(gf.y);
        A4.z = sigf(gf.z); A4.w = sigf(gf.w);
        B4.x = sigf(gi.x) * gh.x; B4.y = sigf(gi.y) * gh.y;
        B4.z = sigf(gi.z) * gh.z; B4.w = sigf(gi.w) * gh.w;
        size_t base = (size_t)(m0 + m) * HDIM + h0 + h4;
        *(float4*)&g_A [base] = A4;
        *(float4*)&g_Bv[base] = B4;
    }
    __syncthreads();

    /* ---- fused chunk summary: 2 chunks x 32 h, 4-way fold (L2-hot) ---- */
    {
        const int q = tid >> 6, l = tid & 63;
        const int cl = l >> 5, hl = l & 31;
        const int bb = m0 >> 12;
        const int lr0 = cl * 64 + q * 16;
        const int* ip = is_init + bb * TLEN + (m0 & 4095) + lr0;
        size_t gidx = ((size_t)(m0 + lr0)) * HDIM + h0 + hl;
        float A = 1.f, Bv = 0.f, r = 0.f;
        #pragma unroll
        for (int s = 0; s < 16; ++s, gidx += HDIM) {
            float a  = g_A[gidx];
            float bv = g_Bv[gidx];
            if (ip[s]) { A = a; Bv = bv; r = 1.f; }
            else       { Bv = fmaf(a, Bv, bv); A *= a; }
        }
        float* PA = (float*)(smem + G1_PA);
        float* PB = (float*)(smem + G1_PB);
        float* PR = (float*)(smem + G1_PR);
        PA[q * 64 + l] = A; PB[q * 64 + l] = Bv; PR[q * 64 + l] = r;
    }
    __syncthreads();
    if (tid < 64) {
        const int l = tid, cl = l >> 5, hl = l & 31;
        float* PA = (float*)(smem + G1_PA);
        float* PB = (float*)(smem + G1_PB);
        float* PR = (float*)(smem + G1_PR);
        float A = PA[l], Bv = PB[l], r = PR[l];
        #pragma unroll
        for (int q = 1; q < 4; ++q) {
            float A2 = PA[q * 64 + l], B2 = PB[q * 64 + l], r2 = PR[q * 64 + l];
            if (r2 > 0.f) { A = A2; Bv = B2; r = 1.f; }
            else          { Bv = fmaf(A2, Bv, B2); A *= A2; }
        }
        const int bb = m0 >> 12, c0 = (m0 & 4095) >> 6;
        int sidx = (bb * NC + c0 + cl) * HDIM + h0 + hl;
        g_sA[sidx] = A; g_sB[sidx] = Bv; g_sR[sidx] = r;
    }
}

/* =========================================================================
 * Output GEMM: out = h_fp16 @ W_out_fp16 (single pass).  256 thr,
 * CTA 64m x 128n, K=512 in 16 chunks. Warps 2m x 4n -> warp 32m x 32n.
 * 4-stage pipeline, skewed ks order. 2 CTAs/SM.
 * Stage: A 64x80 = 5120, B 128x80 = 10240 -> 15360.
 * ========================================================================= */
#define G2_B    5120
#define G2_STG  15360
#define G2_SMEM (4 * G2_STG)     /* 61440 */

__global__ __launch_bounds__(256, 2) void out_mma_kernel(float* __restrict__ out)
{
    extern __shared__ char smem[];
    uint32_t sb = smem_u32(smem);
    const int tid = threadIdx.x, lane = tid & 31, wid = tid >> 5;
    const int m0 = blockIdx.x * 64, n0 = blockIdx.y * 128;
    const int wm = wid >> 2, wn = wid & 3;     /* 2m x 4n */
    const int phase = (wid >> 2) & 1;

    float acc[2][4][4];
    #pragma unroll
    for (int a = 0; a < 2; ++a)
        #pragma unroll
        for (int b = 0; b < 4; ++b)
            acc[a][b][0] = acc[a][b][1] = acc[a][b][2] = acc[a][b][3] = 0.f;

    const char* aG = (const char*)g_h_hi;
    const char* bG = (const char*)g_wo_h;

    /* 768 segments, 3 per thread */
    #define G2_LOAD(c) do {                                                   \
        uint32_t stg = sb + ((c) & 3) * G2_STG;                               \
        int k0 = (c) * 32;                                                    \
        _Pragma("unroll")                                                     \
        for (int it = 0; it < 3; ++it) {                                      \
            int idx = tid + it * 256;                                         \
            if (idx < 256) {                                                  \
                int r = idx >> 2, sg = idx & 3;                               \
                const char* src = aG                                          \
                    + ((size_t)(m0 + r) * HDIM + k0) * 2 + sg * 16;           \
                CP_ASYNC16(stg + r * 80 + sg * 16, src);                      \
            } else {                                                          \
                int j = idx - 256;                                            \
                int r = j >> 2, sg = j & 3;                                   \
                const char* src = bG                                          \
                    + ((size_t)(n0 + r) * HDIM + k0) * 2 + sg * 16;           \
                CP_ASYNC16(stg + G2_B + r * 80 + sg * 16, src);               \
            }                                                                 \
        }                                                                     \
        CP_COMMIT();                                                          \
    } while (0)

    G2_LOAD(0); G2_LOAD(1); G2_LOAD(2);
    #pragma unroll 1
    for (int c = 0; c < 16; ++c) {
        if (c <= 13)      { CP_WAIT(2); }
        else if (c == 14) { CP_WAIT(1); }
        else              { CP_WAIT(0); }
        __syncthreads();
        if (c + 3 < 16) G2_LOAD(c + 3);
        uint32_t stg = sb + (c & 3) * G2_STG;

        #pragma unroll
        for (int kss = 0; kss < 2; ++kss) {
            const int ks = kss ^ phase;
            const int kb = ks * 32;
            uint32_t ah[2][4];
            #pragma unroll
            for (int mi = 0; mi < 2; ++mi) {
                uint32_t ad = stg
                    + (wm * 32 + mi * 16 + (lane & 15)) * 80
                    + (lane >> 4) * 16 + kb;
                ldsm4(ah[mi], ad);
            }
            #pragma unroll
            for (int j = 0; j < 2; ++j) {
                uint32_t bh[4];
                int r = wn * 32 + j * 16 + ((lane >> 4) << 3) + (lane & 7);
                uint32_t bd = stg + G2_B + r * 80
                    + ((lane >> 3) & 1) * 16 + kb;
                ldsm4(bh, bd);
                #pragma unroll
                for (int mi = 0; mi < 2; ++mi)
                    #pragma unroll
                    for (int s = 0; s < 2; ++s) {
                        int nb = j * 2 + s;
                        mma_f16(acc[mi][nb], ah[mi], bh[s*2], bh[s*2+1]);
                    }
            }
        }
    }

    /* direct epilogue */
    #pragma unroll
    for (int mi = 0; mi < 2; ++mi)
        #pragma unroll
        for (int nb = 0; nb < 4; ++nb) {
            int row = m0 + wm * 32 + mi * 16 + (lane >> 2);
            int col = n0 + wn * 32 + nb * 8 + (lane & 3) * 2;
            *(float2*)&out[(size_t)row * OUTF + col] =
                make_float2(acc[mi][nb][0], acc[mi][nb][1]);
            *(float2*)&out[(size_t)(row + 8) * OUTF + col] =
                make_float2(acc[mi][nb][2], acc[mi][nb][3]);
        }
}

/* ======================== scan kernels ================================== */
__global__ void chunk_scan_kernel(const float* __restrict__ h0p)
{
    int lane = blockIdx.x * blockDim.x + threadIdx.x;   /* < BSZ*H */
    int h = lane & (HDIM - 1);
    int b = lane >> 9;
    float h0v = h0p[b * HDIM + h];
    float hp = h0v;
    #pragma unroll 4
    for (int c = 0; c < NC; ++c) {
        int s = (b * NC + c) * HDIM + h;
        g_bound[s] = hp;
        float prev = (g_sR[s] > 0.f) ? h0v : hp;
        hp = fmaf(g_sA[s], prev, g_sB[s]);
    }
}

__global__ void apply_scan_kernel(const int* __restrict__ is_init,
                                  const float* __restrict__ h0p,
                                  float* __restrict__ hn_out)
{
    int lane = blockIdx.x * blockDim.x + threadIdx.x;
    int h  = lane & (HDIM - 1);
    int bc = lane >> 9;
    int c  = bc & (NC - 1);
    int b  = bc >> 6;
    int t0 = c * CHUNK;

    float h0v = h0p[b * HDIM + h];
    float hv  = g_bound[lane];
    size_t idx = ((size_t)(b * TLEN + t0)) * HDIM + h;
    const int* ip = is_init + b * TLEN + t0;

    #pragma unroll 4
    for (int t = 0; t < CHUNK; ++t, idx += HDIM) {
        float a  = g_A[idx];
        float bv = g_Bv[idx];
        float prev = ip[t] ? h0v : hv;
        hv = fmaf(a, prev, bv);
        g_h_hi[idx] = __half_as_ushort(__float2half_rn(hv));
    }
    if (c == NC - 1) hn_out[b * HDIM + h] = hv;
}

/* ========================================================================= */
extern "C" void kernel_launch(void* const* d_in, const int* in_sizes, int n_in,
                              void* d_out, int out_size)
{
    const float* inp  = (const float*)d_in[0];   /* (8,4096,256)  */
    const int*   isin = (const int*)  d_in[1];   /* (8,4096,1)    */
    const float* h0   = (const float*)d_in[2];   /* (8,1,512)     */
    const float* Whg  = (const float*)d_in[3];   /* (256,1536)    */
    const float* Wout = (const float*)d_in[4];   /* (512,256)     */
    float* out = (float*)d_out;                  /* out then h_n  */

    cudaFuncSetAttribute(gates_mma_kernel,
                         cudaFuncAttributeMaxDynamicSharedMemorySize, G1_SMEM);
    cudaFuncSetAttribute(out_mma_kernel,
                         cudaFuncAttributeMaxDynamicSharedMemorySize, G2_SMEM);

    conv_input_kernel<<<(MROWS * INF / 4) / 256, 256>>>(inp);
    conv_whg_kernel<<<(3 * HDIM * INF) / 256, 256>>>(Whg);
    conv_wout_kernel<<<(OUTF * HDIM) / 256, 256>>>(Wout);

    gates_mma_kernel<<<dim3(MROWS / 128, HDIM / 32), 256, G1_SMEM>>>(isin);

    chunk_scan_kernel<<<(BSZ * HDIM) / 256, 256>>>(h0);
    apply_scan_kernel<<<(BSZ * NC * HDIM) / 256, 256>>>(isin, h0,
                                                        out + (size_t)MROWS * OUTF);

    out_mma_kernel<<<dim3(MROWS / 64, OUTF / 128), 256, G2_SMEM>>>(out);
}

// round 16
// speedup vs baseline: 1.2395x; 1.0349x over previous
#include <cuda_runtime.h>
#include <cuda_fp16.h>
#include <cstdint>
#include <math.h>

#define BSZ   8
#define TLEN  4096
#define INF   256
#define HDIM  512
#define OUTF  256
#define MROWS (BSZ*TLEN)     /* 32768 */
#define CHUNK 64
#define NC    (TLEN/CHUNK)   /* 64 */

/* ---------------- scratch (device globals; no runtime allocation) -------- */
__device__ __align__(16) __half g_A [(size_t)MROWS*HDIM];     /* fp16 now */
__device__ __align__(16) __half g_Bv[(size_t)MROWS*HDIM];     /* fp16 now */
__device__ __align__(16) unsigned short g_in_h[(size_t)MROWS*INF];     /* fp16 */
__device__ __align__(16) unsigned short g_Wg_hi[3*HDIM*INF];  /* [1536][256] */
__device__ __align__(16) unsigned short g_Wg_lo[3*HDIM*INF];
__device__ __align__(16) unsigned short g_wo_h[OUTF*HDIM];    /* [256][512]  */
__device__ __align__(16) unsigned short g_h_hi[(size_t)MROWS*HDIM];
__device__ __align__(16) float g_sA[BSZ*NC*HDIM];
__device__ __align__(16) float g_sB[BSZ*NC*HDIM];
__device__ __align__(16) float g_sR[BSZ*NC*HDIM];
__device__ __align__(16) float g_bound[BSZ*NC*HDIM];

__device__ __forceinline__ float sigf(float x) {
    return 1.0f / (1.0f + __expf(-x));
}

__device__ __forceinline__ uint32_t smem_u32(const void* p) {
    uint32_t a;
    asm("{ .reg .u64 t; cvta.to.shared.u64 t, %1; cvt.u32.u64 %0, t; }"
        : "=r"(a) : "l"(p));
    return a;
}

#define CP_ASYNC16(dst, src) \
    asm volatile("cp.async.cg.shared.global [%0], [%1], 16;" :: "r"(dst), "l"(src))
#define CP_COMMIT()  asm volatile("cp.async.commit_group;" ::: "memory")
#define CP_WAIT(N)   asm volatile("cp.async.wait_group %0;" :: "n"(N) : "memory")

__device__ __forceinline__ void ldsm4(uint32_t r[4], uint32_t addr) {
    asm volatile("ldmatrix.sync.aligned.m8n8.x4.shared.b16 {%0,%1,%2,%3}, [%4];"
        : "=r"(r[0]), "=r"(r[1]), "=r"(r[2]), "=r"(r[3]) : "r"(addr));
}

__device__ __forceinline__ void mma_f16(float c[4], const uint32_t a[4],
                                        uint32_t b0, uint32_t b1) {
    asm volatile(
        "mma.sync.aligned.m16n8k16.row.col.f32.f16.f16.f32 "
        "{%0,%1,%2,%3}, {%4,%5,%6,%7}, {%8,%9}, {%0,%1,%2,%3};"
        : "+f"(c[0]), "+f"(c[1]), "+f"(c[2]), "+f"(c[3])
        : "r"(a[0]), "r"(a[1]), "r"(a[2]), "r"(a[3]), "r"(b0), "r"(b1));
}

/* ====================== conversion / split kernels ======================= */
__global__ void conv_input_kernel(const float* __restrict__ x)
{
    int i = blockIdx.x * blockDim.x + threadIdx.x;       /* per float4 */
    float4 v = ((const float4*)x)[i];
    ushort4 hv;
    hv.x = __half_as_ushort(__float2half_rn(v.x));
    hv.y = __half_as_ushort(__float2half_rn(v.y));
    hv.z = __half_as_ushort(__float2half_rn(v.z));
    hv.w = __half_as_ushort(__float2half_rn(v.w));
    ((ushort4*)g_in_h)[i] = hv;
}

__global__ void conv_whg_kernel(const float* __restrict__ W)
{
    int i = blockIdx.x * blockDim.x + threadIdx.x;  /* i = n*256 + k */
    int n = i >> 8, k = i & 255;
    float v = W[(size_t)k * (3 * HDIM) + n];
    __half h = __float2half_rn(v);
    g_Wg_hi[i] = __half_as_ushort(h);
    g_Wg_lo[i] = __half_as_ushort(__float2half_rn(v - __half2float(h)));
}

__global__ void conv_wout_kernel(const float* __restrict__ W)
{
    int i = blockIdx.x * blockDim.x + threadIdx.x;  /* i = n*512 + k */
    int n = i >> 9, k = i & 511;
    g_wo_h[i] = __half_as_ushort(__float2half_rn(W[(size_t)k * OUTF + n]));
}

/* =========================================================================
 * Gates GEMM (fp16 2-pass) + fused sigmoid + fused chunk summary.
 * CTA: 256 thr, 128 m x 96 n (3 gates x 32 h). Warps 4m x 2n -> 32m x 48n.
 * K=256 in 8 chunks of 32, 4-stage cp.async pipeline. 2 CTAs/SM.
 * g_A/g_Bv stored fp16 (halved store traffic); fold reads same fp16 vals.
 * ========================================================================= */
#define G1_B    10240
#define G1_STG  25600
#define G1_PA   51200
#define G1_PB   52224
#define G1_PR   53248
#define G1_SMEM (4 * G1_STG)     /* 102400 */
#define SPITCH  100

__global__ __launch_bounds__(256, 2)
void gates_mma_kernel(const int* __restrict__ is_init)
{
    extern __shared__ char smem[];
    uint32_t sb = smem_u32(smem);
    const int tid = threadIdx.x, lane = tid & 31, wid = tid >> 5;
    const int m0 = blockIdx.x * 128, h0 = blockIdx.y * 32;
    const int wm = wid >> 1, wn = wid & 1;     /* 4m x 2n */
    const int phase = (wid >> 2) & 1;          /* per-SMSP phase skew */

    float acc[2][6][4];
    #pragma unroll
    for (int a = 0; a < 2; ++a)
        #pragma unroll
        for (int b = 0; b < 6; ++b)
            acc[a][b][0] = acc[a][b][1] = acc[a][b][2] = acc[a][b][3] = 0.f;

    const char* aG = (const char*)g_in_h;
    const char* bH = (const char*)g_Wg_hi;
    const char* bL = (const char*)g_Wg_lo;

    /* ---- chunk loader: 1280 x 16B segments, 5 per thread ---- */
    #define G1_LOAD(c) do {                                                   \
        uint32_t stg = sb + ((c) & 3) * G1_STG;                               \
        int k0 = (c) * 32;                                                    \
        _Pragma("unroll")                                                     \
        for (int it = 0; it < 5; ++it) {                                      \
            int idx = tid + it * 256;                                         \
            if (idx < 512) {                                                  \
                int r = idx >> 2, sg = idx & 3;                               \
                const char* src = aG                                          \
                    + ((size_t)(m0 + r) * INF + k0) * 2 + sg * 16;            \
                CP_ASYNC16(stg + r * 80 + sg * 16, src);                      \
            } else {                                                          \
                int j = idx - 512;                                            \
                int sp = (j >= 384) ? 1 : 0, rem = j - sp * 384;              \
                int r = rem >> 2, sg = rem & 3;                               \
                int n = (r >> 5) * HDIM + h0 + (r & 31);                      \
                const char* src = (sp ? bL : bH)                              \
                    + ((size_t)n * INF + k0) * 2 + sg * 16;                   \
                CP_ASYNC16(stg + G1_B + (sp * 96 + r) * 80 + sg * 16, src);   \
            }                                                                 \
        }                                                                     \
        CP_COMMIT();                                                          \
    } while (0)

    G1_LOAD(0); G1_LOAD(1); G1_LOAD(2);
    #pragma unroll 1
    for (int c = 0; c < 8; ++c) {
        if (c <= 5)      { CP_WAIT(2); }
        else if (c == 6) { CP_WAIT(1); }
        else             { CP_WAIT(0); }
        __syncthreads();
        if (c + 3 < 8) G1_LOAD(c + 3);
        uint32_t stg = sb + (c & 3) * G1_STG;

        #pragma unroll
        for (int kss = 0; kss < 2; ++kss) {
            const int ks = kss ^ phase;             /* skewed half-step */
            const int kb = ks * 32;                 /* 16 elems = 32 bytes */
            uint32_t ah[2][4];
            #pragma unroll
            for (int mi = 0; mi < 2; ++mi) {
                uint32_t ad = stg
                    + (wm * 32 + mi * 16 + (lane & 15)) * 80
                    + (lane >> 4) * 16 + kb;
                ldsm4(ah[mi], ad);
            }
            #pragma unroll
            for (int j = 0; j < 3; ++j) {
                uint32_t bh[4], bl[4];
                int r = wn * 48 + j * 16 + ((lane >> 4) << 3) + (lane & 7);
                uint32_t bd = stg + G1_B + r * 80
                    + ((lane >> 3) & 1) * 16 + kb;
                ldsm4(bh, bd);
                ldsm4(bl, bd + 96 * 80);
                #pragma unroll
                for (int mi = 0; mi < 2; ++mi)
                    #pragma unroll
                    for (int s = 0; s < 2; ++s) {
                        int nb = j * 2 + s;
                        mma_f16(acc[mi][nb], ah[mi], bh[s*2], bh[s*2+1]);
                        mma_f16(acc[mi][nb], ah[mi], bl[s*2], bl[s*2+1]);
                    }
            }
        }
    }
    __syncthreads();

    /* ---- epilogue: stage accums, fuse sigmoid, store fp16 ---- */
    float* spad = (float*)smem;
    #pragma unroll
    for (int mi = 0; mi < 2; ++mi)
        #pragma unroll
        for (int nb = 0; nb < 6; ++nb) {
            int row = wm * 32 + mi * 16 + (lane >> 2);
            int col = wn * 48 + nb * 8 + (lane & 3) * 2;
            spad[row * SPITCH + col]           = acc[mi][nb][0];
            spad[row * SPITCH + col + 1]       = acc[mi][nb][1];
            spad[(row + 8) * SPITCH + col]     = acc[mi][nb][2];
            spad[(row + 8) * SPITCH + col + 1] = acc[mi][nb][3];
        }
    __syncthreads();

    const int h4 = (tid & 7) * 4, mr = tid >> 3;     /* mr: 0..31 */
    #pragma unroll
    for (int i = 0; i < 4; ++i) {
        int m = mr + i * 32;
        float4 gf = *(float4*)&spad[m * SPITCH + h4];
        float4 gi = *(float4*)&spad[m * SPITCH + 32 + h4];
        float4 gh = *(float4*)&spad[m * SPITCH + 64 + h4];
        size_t base = (size_t)(m0 + m) * HDIM + h0 + h4;
        __half2 a01 = __floats2half2_rn(sigf(gf.x), sigf(gf.y));
        __half2 a23 = __floats2half2_rn(sigf(gf.z), sigf(gf.w));
        __half2 b01 = __floats2half2_rn(sigf(gi.x) * gh.x, sigf(gi.y) * gh.y);
        __half2 b23 = __floats2half2_rn(sigf(gi.z) * gh.z, sigf(gi.w) * gh.w);
        *(__half2*)&g_A [base]     = a01;
        *(__half2*)&g_A [base + 2] = a23;
        *(__half2*)&g_Bv[base]     = b01;
        *(__half2*)&g_Bv[base + 2] = b23;
    }
    __syncthreads();

    /* ---- fused chunk summary: 2 chunks x 32 h, 4-way fold (L2-hot) ---- */
    {
        const int q = tid >> 6, l = tid & 63;
        const int cl = l >> 5, hl = l & 31;
        const int bb = m0 >> 12;
        const int lr0 = cl * 64 + q * 16;
        const int* ip = is_init + bb * TLEN + (m0 & 4095) + lr0;
        size_t gidx = ((size_t)(m0 + lr0)) * HDIM + h0 + hl;
        float A = 1.f, Bv = 0.f, r = 0.f;
        #pragma unroll
        for (int s = 0; s < 16; ++s, gidx += HDIM) {
            float a  = __half2float(g_A[gidx]);
            float bv = __half2float(g_Bv[gidx]);
            if (ip[s]) { A = a; Bv = bv; r = 1.f; }
            else       { Bv = fmaf(a, Bv, bv); A *= a; }
        }
        float* PA = (float*)(smem + G1_PA);
        float* PB = (float*)(smem + G1_PB);
        float* PR = (float*)(smem + G1_PR);
        PA[q * 64 + l] = A; PB[q * 64 + l] = Bv; PR[q * 64 + l] = r;
    }
    __syncthreads();
    if (tid < 64) {
        const int l = tid, cl = l >> 5, hl = l & 31;
        float* PA = (float*)(smem + G1_PA);
        float* PB = (float*)(smem + G1_PB);
        float* PR = (float*)(smem + G1_PR);
        float A = PA[l], Bv = PB[l], r = PR[l];
        #pragma unroll
        for (int q = 1; q < 4; ++q) {
            float A2 = PA[q * 64 + l], B2 = PB[q * 64 + l], r2 = PR[q * 64 + l];
            if (r2 > 0.f) { A = A2; Bv = B2; r = 1.f; }
            else          { Bv = fmaf(A2, Bv, B2); A *= A2; }
        }
        const int bb = m0 >> 12, c0 = (m0 & 4095) >> 6;
        int sidx = (bb * NC + c0 + cl) * HDIM + h0 + hl;
        g_sA[sidx] = A; g_sB[sidx] = Bv; g_sR[sidx] = r;
    }
}

/* =========================================================================
 * Output GEMM: out = h_fp16 @ W_out_fp16 (single pass).  256 thr,
 * CTA 64m x 128n, K=512 in 16 chunks. Warps 2m x 4n -> warp 32m x 32n.
 * 4-stage pipeline, skewed ks order. 2 CTAs/SM.
 * ========================================================================= */
#define G2_B    5120
#define G2_STG  15360
#define G2_SMEM (4 * G2_STG)     /* 61440 */

__global__ __launch_bounds__(256, 2) void out_mma_kernel(float* __restrict__ out)
{
    extern __shared__ char smem[];
    uint32_t sb = smem_u32(smem);
    const int tid = threadIdx.x, lane = tid & 31, wid = tid >> 5;
    const int m0 = blockIdx.x * 64, n0 = blockIdx.y * 128;
    const int wm = wid >> 2, wn = wid & 3;     /* 2m x 4n */
    const int phase = (wid >> 2) & 1;

    float acc[2][4][4];
    #pragma unroll
    for (int a = 0; a < 2; ++a)
        #pragma unroll
        for (int b = 0; b < 4; ++b)
            acc[a][b][0] = acc[a][b][1] = acc[a][b][2] = acc[a][b][3] = 0.f;

    const char* aG = (const char*)g_h_hi;
    const char* bG = (const char*)g_wo_h;

    /* 768 segments, 3 per thread */
    #define G2_LOAD(c) do {                                                   \
        uint32_t stg = sb + ((c) & 3) * G2_STG;                               \
        int k0 = (c) * 32;                                                    \
        _Pragma("unroll")                                                     \
        for (int it = 0; it < 3; ++it) {                                      \
            int idx = tid + it * 256;                                         \
            if (idx < 256) {                                                  \
                int r = idx >> 2, sg = idx & 3;                               \
                const char* src = aG                                          \
                    + ((size_t)(m0 + r) * HDIM + k0) * 2 + sg * 16;           \
                CP_ASYNC16(stg + r * 80 + sg * 16, src);                      \
            } else {                                                          \
                int j = idx - 256;                                            \
                int r = j >> 2, sg = j & 3;                                   \
                const char* src = bG                                          \
                    + ((size_t)(n0 + r) * HDIM + k0) * 2 + sg * 16;           \
                CP_ASYNC16(stg + G2_B + r * 80 + sg * 16, src);               \
            }                                                                 \
        }                                                                     \
        CP_COMMIT();                                                          \
    } while (0)

    G2_LOAD(0); G2_LOAD(1); G2_LOAD(2);
    #pragma unroll 1
    for (int c = 0; c < 16; ++c) {
        if (c <= 13)      { CP_WAIT(2); }
        else if (c == 14) { CP_WAIT(1); }
        else              { CP_WAIT(0); }
        __syncthreads();
        if (c + 3 < 16) G2_LOAD(c + 3);
        uint32_t stg = sb + (c & 3) * G2_STG;

        #pragma unroll
        for (int kss = 0; kss < 2; ++kss) {
            const int ks = kss ^ phase;
            const int kb = ks * 32;
            uint32_t ah[2][4];
            #pragma unroll
            for (int mi = 0; mi < 2; ++mi) {
                uint32_t ad = stg
                    + (wm * 32 + mi * 16 + (lane & 15)) * 80
                    + (lane >> 4) * 16 + kb;
                ldsm4(ah[mi], ad);
            }
            #pragma unroll
            for (int j = 0; j < 2; ++j) {
                uint32_t bh[4];
                int r = wn * 32 + j * 16 + ((lane >> 4) << 3) + (lane & 7);
                uint32_t bd = stg + G2_B + r * 80
                    + ((lane >> 3) & 1) * 16 + kb;
                ldsm4(bh, bd);
                #pragma unroll
                for (int mi = 0; mi < 2; ++mi)
                    #pragma unroll
                    for (int s = 0; s < 2; ++s) {
                        int nb = j * 2 + s;
                        mma_f16(acc[mi][nb], ah[mi], bh[s*2], bh[s*2+1]);
                    }
            }
        }
    }

    /* direct epilogue */
    #pragma unroll
    for (int mi = 0; mi < 2; ++mi)
        #pragma unroll
        for (int nb = 0; nb < 4; ++nb) {
            int row = m0 + wm * 32 + mi * 16 + (lane >> 2);
            int col = n0 + wn * 32 + nb * 8 + (lane & 3) * 2;
            *(float2*)&out[(size_t)row * OUTF + col] =
                make_float2(acc[mi][nb][0], acc[mi][nb][1]);
            *(float2*)&out[(size_t)(row + 8) * OUTF + col] =
                make_float2(acc[mi][nb][2], acc[mi][nb][3]);
        }
}

/* ======================== scan kernels ================================== */
__global__ void chunk_scan_kernel(const float* __restrict__ h0p)
{
    int lane = blockIdx.x * blockDim.x + threadIdx.x;   /* < BSZ*H */
    int h = lane & (HDIM - 1);
    int b = lane >> 9;
    float h0v = h0p[b * HDIM + h];
    float hp = h0v;
    #pragma unroll 4
    for (int c = 0; c < NC; ++c) {
        int s = (b * NC + c) * HDIM + h;
        g_bound[s] = hp;
        float prev = (g_sR[s] > 0.f) ? h0v : hp;
        hp = fmaf(g_sA[s], prev, g_sB[s]);
    }
}

/* half2-vectorized: each thread owns 2 adjacent h columns */
__global__ void apply_scan_kernel(const int* __restrict__ is_init,
                                  const float* __restrict__ h0p,
                                  float* __restrict__ hn_out)
{
    int lane = blockIdx.x * blockDim.x + threadIdx.x;   /* < BSZ*NC*HDIM/2 */
    int hp2 = lane & (HDIM / 2 - 1);    /* 256 column pairs */
    int bc = lane >> 8;
    int c  = bc & (NC - 1);
    int b  = bc >> 6;
    int t0 = c * CHUNK;

    float2 h0v = ((const float2*)h0p)[b * (HDIM / 2) + hp2];
    float2 hv  = ((const float2*)g_bound)[(b * NC + c) * (HDIM / 2) + hp2];
    size_t idx = ((size_t)(b * TLEN + t0)) * (HDIM / 2) + hp2;  /* half2 units */
    const int* ip = is_init + b * TLEN + t0;
    const __half2* A2 = (const __half2*)g_A;
    const __half2* B2 = (const __half2*)g_Bv;
    __half2* H2 = (__half2*)g_h_hi;

    #pragma unroll 4
    for (int t = 0; t < CHUNK; ++t, idx += HDIM / 2) {
        float2 a  = __half22float2(A2[idx]);
        float2 bv = __half22float2(B2[idx]);
        float2 prev = ip[t] ? h0v : hv;
        hv.x = fmaf(a.x, prev.x, bv.x);
        hv.y = fmaf(a.y, prev.y, bv.y);
        H2[idx] = __floats2half2_rn(hv.x, hv.y);
    }
    if (c == NC - 1)
        ((float2*)hn_out)[b * (HDIM / 2) + hp2] = hv;
}

/* ========================================================================= */
extern "C" void kernel_launch(void* const* d_in, const int* in_sizes, int n_in,
                              void* d_out, int out_size)
{
    const float* inp  = (const float*)d_in[0];   /* (8,4096,256)  */
    const int*   isin = (const int*)  d_in[1];   /* (8,4096,1)    */
    const float* h0   = (const float*)d_in[2];   /* (8,1,512)     */
    const float* Whg  = (const float*)d_in[3];   /* (256,1536)    */
    const float* Wout = (const float*)d_in[4];   /* (512,256)     */
    float* out = (float*)d_out;                  /* out then h_n  */

    cudaFuncSetAttribute(gates_mma_kernel,
                         cudaFuncAttributeMaxDynamicSharedMemorySize, G1_SMEM);
    cudaFuncSetAttribute(out_mma_kernel,
                         cudaFuncAttributeMaxDynamicSharedMemorySize, G2_SMEM);

    conv_input_kernel<<<(MROWS * INF / 4) / 256, 256>>>(inp);
    conv_whg_kernel<<<(3 * HDIM * INF) / 256, 256>>>(Whg);
    conv_wout_kernel<<<(OUTF * HDIM) / 256, 256>>>(Wout);

    gates_mma_kernel<<<dim3(MROWS / 128, HDIM / 32), 256, G1_SMEM>>>(isin);

    chunk_scan_kernel<<<(BSZ * HDIM) / 256, 256>>>(h0);
    apply_scan_kernel<<<(BSZ * NC * HDIM / 2) / 256, 256>>>(isin, h0,
                                                        out + (size_t)MROWS * OUTF);

    out_mma_kernel<<<dim3(MROWS / 64, OUTF / 128), 256, G2_SMEM>>>(out);
}